// round 1
// baseline (speedup 1.0000x reference)
#include <cuda_runtime.h>
#include <math.h>

// Problem constants
#define Ecols 768
#define NHEAD 12
#define NWIRE 8
#define DKDIM 64
#define NK 17            // 16 feature rows + 1 bias row
#define NSPLIT 4         // i-dimension split for precompute

// Scratch (allocation-free: __device__ globals)
__device__ __align__(16) float d_M[16 * Ecols];      // rank-16 folded matrix [16][768]
__device__ __align__(16) float d_beff[Ecols];        // folded bias [768]
__device__ float d_part[NSPLIT * NK * Ecols];        // split-K partials

#define PACK2(dst, f)   asm("mov.b64 %0, {%1, %1};" : "=l"(dst) : "f"(f))
#define FMA2(acc, a, b) asm("fma.rn.f32x2 %0, %1, %2, %0;" : "+l"(acc) : "l"(a), "l"(b))

// ---------------------------------------------------------------------------
// K1: precompute partial M = H @ W_out  (H folded from theta/W_proj on the fly)
// grid = (24 e-tiles, 4 i-splits), 256 threads = 32 e-lanes x 8 i-groups
// ---------------------------------------------------------------------------
__global__ void k_pre(const float* __restrict__ theta,
                      const float* __restrict__ Wp,
                      const float* __restrict__ bp,
                      const float* __restrict__ Wout) {
    const int b  = blockIdx.x;          // e tile 0..23 (32 cols each)
    const int s  = blockIdx.y;          // i split 0..3 (192 rows each)
    const int t  = threadIdx.x;
    const int el = t & 31;
    const int ig = t >> 5;
    const int e  = b * 32 + el;
    const int i0 = s * 192;

    __shared__ __align__(16) float sHT[192][16];   // H^T slice: [i][k]
    __shared__ float sB[192];                      // b_proj slice
    __shared__ float red[8][NK][32];               // ig-reduction

    if (t < 192) {
        const int i = i0 + t;
        const int h = i >> 6;
        const int d = i & 63;
        sB[t] = bp[i];
#pragma unroll
        for (int w = 0; w < 8; ++w) {
            const float p = Wp[(h * NWIRE + w) * DKDIM + d];
            float sn, cs;
            sincosf(theta[h * NWIRE + w], &sn, &cs);
            sHT[t][w]     = cs * p;    // cos-feature row
            sHT[t][8 + w] = -sn * p;   // sin-feature row (sign folded in)
        }
    }
    __syncthreads();

    float acc[NK];
#pragma unroll
    for (int k = 0; k < NK; ++k) acc[k] = 0.f;

    for (int ii = ig * 24; ii < ig * 24 + 24; ++ii) {
        const float wv = Wout[(i0 + ii) * Ecols + e];   // coalesced across el
        const float4 h0 = *(const float4*)&sHT[ii][0];
        const float4 h1 = *(const float4*)&sHT[ii][4];
        const float4 h2 = *(const float4*)&sHT[ii][8];
        const float4 h3 = *(const float4*)&sHT[ii][12];
        acc[0]  += h0.x * wv;  acc[1]  += h0.y * wv;
        acc[2]  += h0.z * wv;  acc[3]  += h0.w * wv;
        acc[4]  += h1.x * wv;  acc[5]  += h1.y * wv;
        acc[6]  += h1.z * wv;  acc[7]  += h1.w * wv;
        acc[8]  += h2.x * wv;  acc[9]  += h2.y * wv;
        acc[10] += h2.z * wv;  acc[11] += h2.w * wv;
        acc[12] += h3.x * wv;  acc[13] += h3.y * wv;
        acc[14] += h3.z * wv;  acc[15] += h3.w * wv;
        acc[16] += sB[ii] * wv;
    }

#pragma unroll
    for (int k = 0; k < NK; ++k) red[ig][k][el] = acc[k];
    __syncthreads();

    for (int o = t; o < NK * 32; o += 256) {
        const int k = o >> 5;
        const int l = o & 31;
        float sm = 0.f;
#pragma unroll
        for (int g = 0; g < 8; ++g) sm += red[g][k][l];
        d_part[(s * NK + k) * Ecols + b * 32 + l] = sm;
    }
}

// ---------------------------------------------------------------------------
// K2: reduce split-K partials into d_M / d_beff
// ---------------------------------------------------------------------------
__global__ void k_red(const float* __restrict__ bout) {
    const int idx = blockIdx.x * 256 + threadIdx.x;
    if (idx >= NK * Ecols) return;
    float sm = d_part[idx]
             + d_part[NK * Ecols + idx]
             + d_part[2 * NK * Ecols + idx]
             + d_part[3 * NK * Ecols + idx];
    if (idx < 16 * Ecols) {
        d_M[idx] = sm;
    } else {
        const int e = idx - 16 * Ecols;
        d_beff[e] = sm + bout[e];
    }
}

// ---------------------------------------------------------------------------
// K3: main — per token: 16-dim trig features @ M[16,768] + b_eff
// 192 threads, 4 outputs/thread (2 packed f32x2 accumulators), 16 tokens/block
// M held entirely in registers (16 x 2 packed pairs), features in 1KB smem.
// ---------------------------------------------------------------------------
__global__ void __launch_bounds__(192, 2)
k_main(const float* __restrict__ x, float* __restrict__ out, int NT) {
    const int t = threadIdx.x;
    const int tokBase = blockIdx.x * 16;

    // Load this thread's 4 M-columns (pairs 2t, 2t+1) into registers.
    unsigned long long Ma[16], Mb[16];
#pragma unroll
    for (int w = 0; w < 16; ++w) {
        const ulonglong2 m = *(const ulonglong2*)(d_M + w * Ecols + 4 * t);
        Ma[w] = m.x;
        Mb[w] = m.y;
    }
    const ulonglong2 bv = *(const ulonglong2*)(d_beff + 4 * t);

    __shared__ __align__(16) float feat[16][16];   // [token][slot]; slot<8: cos, >=8: sin

    for (int task = t; task < 256; task += 192) {
        const int tb = task >> 4;
        const int slot = task & 15;
        const int tok = tokBase + tb;
        if (tok < NT) {
            const float xv = x[tok * Ecols + (slot & 7)];
            feat[tb][slot] = (slot < 8) ? cosf(xv) : sinf(xv);
        }
    }
    __syncthreads();

#pragma unroll 2
    for (int tb = 0; tb < 16; ++tb) {
        const int tok = tokBase + tb;
        if (tok >= NT) break;

        const float4 f0 = *(const float4*)&feat[tb][0];
        const float4 f1 = *(const float4*)&feat[tb][4];
        const float4 f2 = *(const float4*)&feat[tb][8];
        const float4 f3 = *(const float4*)&feat[tb][12];

        unsigned long long F[16];
        PACK2(F[0],  f0.x); PACK2(F[1],  f0.y); PACK2(F[2],  f0.z); PACK2(F[3],  f0.w);
        PACK2(F[4],  f1.x); PACK2(F[5],  f1.y); PACK2(F[6],  f1.z); PACK2(F[7],  f1.w);
        PACK2(F[8],  f2.x); PACK2(F[9],  f2.y); PACK2(F[10], f2.z); PACK2(F[11], f2.w);
        PACK2(F[12], f3.x); PACK2(F[13], f3.y); PACK2(F[14], f3.z); PACK2(F[15], f3.w);

        unsigned long long a0 = bv.x;
        unsigned long long a1 = bv.y;
#pragma unroll
        for (int w = 0; w < 16; ++w) {
            FMA2(a0, F[w], Ma[w]);
            FMA2(a1, F[w], Mb[w]);
        }

        *(ulonglong2*)(out + tok * Ecols + 4 * t) = make_ulonglong2(a0, a1);
    }
}

// ---------------------------------------------------------------------------
// Launch: inputs in metadata order: x, theta, W_proj, b_proj, W_out, b_out
// ---------------------------------------------------------------------------
extern "C" void kernel_launch(void* const* d_in, const int* in_sizes, int n_in,
                              void* d_out, int out_size) {
    const float* x     = (const float*)d_in[0];
    const float* theta = (const float*)d_in[1];
    const float* Wp    = (const float*)d_in[2];
    const float* bp    = (const float*)d_in[3];
    const float* Wout  = (const float*)d_in[4];
    const float* bout  = (const float*)d_in[5];
    float* out = (float*)d_out;

    const int NT = in_sizes[0] / Ecols;   // tokens = B*S = 32768

    k_pre<<<dim3(24, NSPLIT), 256>>>(theta, Wp, bp, Wout);
    k_red<<<(NK * Ecols + 255) / 256, 256>>>(bout);
    k_main<<<(NT + 15) / 16, 192>>>(x, out, NT);
}

// round 3
// speedup vs baseline: 1.0297x; 1.0297x over previous
#include <cuda_runtime.h>
#include <math.h>

// Problem constants
#define Ecols 768
#define NHEAD 12
#define NWIRE 8
#define DKDIM 64
#define NK 17            // 16 feature rows + 1 bias row
#define NSPLIT 4         // i-dimension split for precompute

// Scratch (allocation-free: __device__ globals)
__device__ __align__(16) float d_M[16 * Ecols];      // rank-16 folded matrix [16][768]
__device__ __align__(16) float d_beff[Ecols];        // folded bias [768]
__device__ float d_part[NSPLIT * NK * Ecols];        // split-K partials

#define PACK2(dst, f)   asm("mov.b64 %0, {%1, %1};" : "=l"(dst) : "f"(f))
#define FMA2(acc, a, b) asm("fma.rn.f32x2 %0, %1, %2, %0;" : "+l"(acc) : "l"(a), "l"(b))

// ---------------------------------------------------------------------------
// K1: precompute partial M = H @ W_out  (H folded from theta/W_proj on the fly)
// grid = (24 e-tiles, 4 i-splits), 256 threads = 32 e-lanes x 8 i-groups
// ---------------------------------------------------------------------------
__global__ void k_pre(const float* __restrict__ theta,
                      const float* __restrict__ Wp,
                      const float* __restrict__ bp,
                      const float* __restrict__ Wout) {
    const int b  = blockIdx.x;          // e tile 0..23 (32 cols each)
    const int s  = blockIdx.y;          // i split 0..3 (192 rows each)
    const int t  = threadIdx.x;
    const int el = t & 31;
    const int ig = t >> 5;
    const int e  = b * 32 + el;
    const int i0 = s * 192;

    __shared__ __align__(16) float sHT[192][16];   // H^T slice: [i][k]
    __shared__ float sB[192];                      // b_proj slice
    __shared__ float red[8][NK][32];               // ig-reduction

    if (t < 192) {
        const int i = i0 + t;
        const int h = i >> 6;
        const int d = i & 63;
        sB[t] = bp[i];
#pragma unroll
        for (int w = 0; w < 8; ++w) {
            const float p = Wp[(h * NWIRE + w) * DKDIM + d];
            float sn, cs;
            sincosf(theta[h * NWIRE + w], &sn, &cs);
            sHT[t][w]     = cs * p;    // cos-feature row
            sHT[t][8 + w] = -sn * p;   // sin-feature row (sign folded in)
        }
    }
    __syncthreads();

    float acc[NK];
#pragma unroll
    for (int k = 0; k < NK; ++k) acc[k] = 0.f;

    for (int ii = ig * 24; ii < ig * 24 + 24; ++ii) {
        const float wv = Wout[(i0 + ii) * Ecols + e];   // coalesced across el
        const float4 h0 = *(const float4*)&sHT[ii][0];
        const float4 h1 = *(const float4*)&sHT[ii][4];
        const float4 h2 = *(const float4*)&sHT[ii][8];
        const float4 h3 = *(const float4*)&sHT[ii][12];
        acc[0]  += h0.x * wv;  acc[1]  += h0.y * wv;
        acc[2]  += h0.z * wv;  acc[3]  += h0.w * wv;
        acc[4]  += h1.x * wv;  acc[5]  += h1.y * wv;
        acc[6]  += h1.z * wv;  acc[7]  += h1.w * wv;
        acc[8]  += h2.x * wv;  acc[9]  += h2.y * wv;
        acc[10] += h2.z * wv;  acc[11] += h2.w * wv;
        acc[12] += h3.x * wv;  acc[13] += h3.y * wv;
        acc[14] += h3.z * wv;  acc[15] += h3.w * wv;
        acc[16] += sB[ii] * wv;
    }

#pragma unroll
    for (int k = 0; k < NK; ++k) red[ig][k][el] = acc[k];
    __syncthreads();

    for (int o = t; o < NK * 32; o += 256) {
        const int k = o >> 5;
        const int l = o & 31;
        float sm = 0.f;
#pragma unroll
        for (int g = 0; g < 8; ++g) sm += red[g][k][l];
        d_part[(s * NK + k) * Ecols + b * 32 + l] = sm;
    }
}

// ---------------------------------------------------------------------------
// K2: reduce split-K partials into d_M / d_beff
// ---------------------------------------------------------------------------
__global__ void k_red(const float* __restrict__ bout) {
    const int idx = blockIdx.x * 256 + threadIdx.x;
    if (idx >= NK * Ecols) return;
    float sm = d_part[idx]
             + d_part[NK * Ecols + idx]
             + d_part[2 * NK * Ecols + idx]
             + d_part[3 * NK * Ecols + idx];
    if (idx < 16 * Ecols) {
        d_M[idx] = sm;
    } else {
        const int e = idx - 16 * Ecols;
        d_beff[e] = sm + bout[e];
    }
}

// ---------------------------------------------------------------------------
// K3: main — per token: 16-dim trig features @ M[16,768] + b_eff
// 192 threads, 4 outputs/thread (2 packed f32x2 accumulators), 16 tokens/block
// M held entirely in registers (16 x 2 packed pairs), features in 1KB smem.
// ---------------------------------------------------------------------------
__global__ void __launch_bounds__(192, 2)
k_main(const float* __restrict__ x, float* __restrict__ out, int NT) {
    const int t = threadIdx.x;
    const int tokBase = blockIdx.x * 16;

    // Load this thread's 4 M-columns (pairs 2t, 2t+1) into registers.
    unsigned long long Ma[16], Mb[16];
#pragma unroll
    for (int w = 0; w < 16; ++w) {
        const ulonglong2 m = *(const ulonglong2*)(d_M + w * Ecols + 4 * t);
        Ma[w] = m.x;
        Mb[w] = m.y;
    }
    const ulonglong2 bv = *(const ulonglong2*)(d_beff + 4 * t);

    __shared__ __align__(16) float feat[16][16];   // [token][slot]; slot<8: cos, >=8: sin

    for (int task = t; task < 256; task += 192) {
        const int tb = task >> 4;
        const int slot = task & 15;
        const int tok = tokBase + tb;
        if (tok < NT) {
            const float xv = x[tok * Ecols + (slot & 7)];
            feat[tb][slot] = (slot < 8) ? cosf(xv) : sinf(xv);
        }
    }
    __syncthreads();

#pragma unroll 2
    for (int tb = 0; tb < 16; ++tb) {
        const int tok = tokBase + tb;
        if (tok >= NT) break;

        const float4 f0 = *(const float4*)&feat[tb][0];
        const float4 f1 = *(const float4*)&feat[tb][4];
        const float4 f2 = *(const float4*)&feat[tb][8];
        const float4 f3 = *(const float4*)&feat[tb][12];

        unsigned long long F[16];
        PACK2(F[0],  f0.x); PACK2(F[1],  f0.y); PACK2(F[2],  f0.z); PACK2(F[3],  f0.w);
        PACK2(F[4],  f1.x); PACK2(F[5],  f1.y); PACK2(F[6],  f1.z); PACK2(F[7],  f1.w);
        PACK2(F[8],  f2.x); PACK2(F[9],  f2.y); PACK2(F[10], f2.z); PACK2(F[11], f2.w);
        PACK2(F[12], f3.x); PACK2(F[13], f3.y); PACK2(F[14], f3.z); PACK2(F[15], f3.w);

        unsigned long long a0 = bv.x;
        unsigned long long a1 = bv.y;
#pragma unroll
        for (int w = 0; w < 16; ++w) {
            FMA2(a0, F[w], Ma[w]);
            FMA2(a1, F[w], Mb[w]);
        }

        *(ulonglong2*)(out + tok * Ecols + 4 * t) = make_ulonglong2(a0, a1);
    }
}

// ---------------------------------------------------------------------------
// Launch: inputs in metadata order: x, theta, W_proj, b_proj, W_out, b_out
// ---------------------------------------------------------------------------
extern "C" void kernel_launch(void* const* d_in, const int* in_sizes, int n_in,
                              void* d_out, int out_size) {
    const float* x     = (const float*)d_in[0];
    const float* theta = (const float*)d_in[1];
    const float* Wp    = (const float*)d_in[2];
    const float* bp    = (const float*)d_in[3];
    const float* Wout  = (const float*)d_in[4];
    const float* bout  = (const float*)d_in[5];
    float* out = (float*)d_out;

    const int NT = in_sizes[0] / Ecols;   // tokens = B*S = 32768

    k_pre<<<dim3(24, NSPLIT), 256>>>(theta, Wp, bp, Wout);
    k_red<<<(NK * Ecols + 255) / 256, 256>>>(bout);
    k_main<<<(NT + 15) / 16, 192>>>(x, out, NT);
}